// round 2
// baseline (speedup 1.0000x reference)
#include <cuda_runtime.h>
#include <math.h>

// Problem dims
#define HH   8
#define Dm   512
#define DFFm 2048
#define BB   8
#define TT   1024
#define BT   (BB*TT)          // 8192
#define EPSv 1e-5f

// ---------------- scratch (static __device__, allocation-free) ----------------
__device__ float g_q[HH*BT*Dm];          // 128 MB  [H, B*T, D]
__device__ float g_k[HH*BT*Dm];          // 128 MB
__device__ float g_v[HH*BT*Dm];          // 128 MB
__device__ float g_s[(size_t)HH*BB*TT*TT]; // 256 MB [H,B,T,T]
__device__ float g_concat[(size_t)BT*HH*Dm]; // 128 MB [B*T, H*D]
__device__ float g_mha[BT*Dm];           // 16 MB
__device__ float g_y1[BT*Dm];            // 16 MB
__device__ float g_ff1[BT*DFFm];         // 64 MB
__device__ float g_ff2[BT*Dm];           // 16 MB

// ---------------- generic batched SGEMM: C = alpha*A@B(^T) + bias ----------------
// A row-major [M,K] lda ; B row-major [K,N] ldb (TB=0) or [N,K] ldb (TB=1)
// C row-major [M,N] ldc. Batch z: A += z*sA, B += z*sB, bias += z*sBias,
// C += (z/innerB)*sC_outer + (z%innerB)*sC_inner   (innerB==1 -> z*sC_outer)
#define BMt 128
#define BNt 128
#define BKt 16

template<int TB>
__global__ void __launch_bounds__(256, 2)
gemm_kernel(const float* __restrict__ A, const float* __restrict__ Bm,
            const float* __restrict__ bias, float* __restrict__ C,
            int K, int lda, int ldb, int ldc,
            long sA, long sB, long sBias,
            int innerB, long sC_outer, long sC_inner, float alpha)
{
    __shared__ float As[BKt][BMt + 4];
    __shared__ float Bs[BKt][BNt + 4];

    const int z = blockIdx.z;
    const float* Ab = A + (long)z * sA;
    const float* Bb = Bm + (long)z * sB;
    const float* biasb = bias ? (bias + (long)z * sBias) : nullptr;
    long coff;
    if (innerB > 1) coff = (long)(z / innerB) * sC_outer + (long)(z % innerB) * sC_inner;
    else            coff = (long)z * sC_outer;
    float* Cb = C + coff;

    const int mBase = blockIdx.y * BMt;
    const int nBase = blockIdx.x * BNt;
    const int tid = threadIdx.x;
    const int m0 = (tid >> 4) << 3;
    const int n0 = (tid & 15) << 3;

    // loader indices (transposed-store pattern for A and TB=1 B)
    const int tRow = tid >> 2;          // 0..63
    const int tC4  = (tid & 3) << 2;    // 0,4,8,12

    float acc[8][8];
    #pragma unroll
    for (int i = 0; i < 8; i++)
        #pragma unroll
        for (int j = 0; j < 8; j++) acc[i][j] = 0.f;

    for (int k0 = 0; k0 < K; k0 += BKt) {
        // ---- load A tile, store transposed As[k][m]
        #pragma unroll
        for (int l = 0; l < 2; l++) {
            int r = tRow + l * 64;
            float4 va = *(const float4*)(Ab + (long)(mBase + r) * lda + k0 + tC4);
            As[tC4 + 0][r] = va.x; As[tC4 + 1][r] = va.y;
            As[tC4 + 2][r] = va.z; As[tC4 + 3][r] = va.w;
        }
        // ---- load B tile
        if (TB == 0) {
            #pragma unroll
            for (int l = 0; l < 2; l++) {
                int id = tid + l * 256;
                int kr = id >> 5;
                int c  = (id & 31) << 2;
                float4 vb = *(const float4*)(Bb + (long)(k0 + kr) * ldb + nBase + c);
                *(float4*)&Bs[kr][c] = vb;
            }
        } else {
            #pragma unroll
            for (int l = 0; l < 2; l++) {
                int r = tRow + l * 64;
                float4 vb = *(const float4*)(Bb + (long)(nBase + r) * ldb + k0 + tC4);
                Bs[tC4 + 0][r] = vb.x; Bs[tC4 + 1][r] = vb.y;
                Bs[tC4 + 2][r] = vb.z; Bs[tC4 + 3][r] = vb.w;
            }
        }
        __syncthreads();

        #pragma unroll
        for (int k = 0; k < BKt; k++) {
            float a[8], b[8];
            *(float4*)(a)     = *(const float4*)&As[k][m0];
            *(float4*)(a + 4) = *(const float4*)&As[k][m0 + 4];
            *(float4*)(b)     = *(const float4*)&Bs[k][n0];
            *(float4*)(b + 4) = *(const float4*)&Bs[k][n0 + 4];
            #pragma unroll
            for (int i = 0; i < 8; i++)
                #pragma unroll
                for (int j = 0; j < 8; j++)
                    acc[i][j] += a[i] * b[j];
        }
        __syncthreads();
    }

    // ---- epilogue
    #pragma unroll
    for (int i = 0; i < 8; i++) {
        long row = mBase + m0 + i;
        #pragma unroll
        for (int j = 0; j < 8; j += 4) {
            int col = nBase + n0 + j;
            float4 v;
            v.x = acc[i][j + 0] * alpha;
            v.y = acc[i][j + 1] * alpha;
            v.z = acc[i][j + 2] * alpha;
            v.w = acc[i][j + 3] * alpha;
            if (biasb) {
                v.x += biasb[col + 0]; v.y += biasb[col + 1];
                v.z += biasb[col + 2]; v.w += biasb[col + 3];
            }
            *(float4*)(Cb + row * ldc + col) = v;
        }
    }
}

// ---------------- block reductions (256 threads) ----------------
__device__ __forceinline__ float block_sum(float v, float* sm) {
    #pragma unroll
    for (int o = 16; o; o >>= 1) v += __shfl_xor_sync(0xffffffffu, v, o);
    if ((threadIdx.x & 31) == 0) sm[threadIdx.x >> 5] = v;
    __syncthreads();
    if (threadIdx.x < 8) {
        float s = sm[threadIdx.x];
        #pragma unroll
        for (int o = 4; o; o >>= 1) s += __shfl_xor_sync(0xffu, s, o);
        if (threadIdx.x == 0) sm[0] = s;
    }
    __syncthreads();
    float r = sm[0];
    __syncthreads();
    return r;
}

__device__ __forceinline__ float block_max(float v, float* sm) {
    #pragma unroll
    for (int o = 16; o; o >>= 1) v = fmaxf(v, __shfl_xor_sync(0xffffffffu, v, o));
    if ((threadIdx.x & 31) == 0) sm[threadIdx.x >> 5] = v;
    __syncthreads();
    if (threadIdx.x < 8) {
        float s = sm[threadIdx.x];
        #pragma unroll
        for (int o = 4; o; o >>= 1) s = fmaxf(s, __shfl_xor_sync(0xffu, s, o));
        if (threadIdx.x == 0) sm[0] = s;
    }
    __syncthreads();
    float r = sm[0];
    __syncthreads();
    return r;
}

// ---------------- softmax over last dim (rows of length 1024) ----------------
__global__ void __launch_bounds__(256)
softmax_kernel(float* __restrict__ S)
{
    __shared__ float sm[8];
    float* p = S + (size_t)blockIdx.x * TT;
    int t = threadIdx.x;
    float x0 = p[t], x1 = p[t + 256], x2 = p[t + 512], x3 = p[t + 768];
    float m = block_max(fmaxf(fmaxf(x0, x1), fmaxf(x2, x3)), sm);
    float e0 = __expf(x0 - m), e1 = __expf(x1 - m);
    float e2 = __expf(x2 - m), e3 = __expf(x3 - m);
    float s = block_sum(e0 + e1 + e2 + e3, sm);
    float inv = 1.f / s;
    p[t] = e0 * inv; p[t + 256] = e1 * inv;
    p[t + 512] = e2 * inv; p[t + 768] = e3 * inv;
}

// ---------------- fused (optional relu) + residual + LayerNorm ----------------
template<int RELU>
__global__ void __launch_bounds__(256)
add_ln_kernel(const float* __restrict__ a, const float* __restrict__ res,
              const float* __restrict__ g, const float* __restrict__ be,
              float* __restrict__ out)
{
    __shared__ float sm[8];
    long row = blockIdx.x;
    const float* ap = a + row * Dm;
    const float* rp = res + row * Dm;
    int t = threadIdx.x;
    float v0 = ap[t], v1 = ap[t + 256];
    if (RELU) { v0 = fmaxf(v0, 0.f); v1 = fmaxf(v1, 0.f); }
    v0 += rp[t]; v1 += rp[t + 256];
    float mean = block_sum(v0 + v1, sm) * (1.f / Dm);
    float d0 = v0 - mean, d1 = v1 - mean;
    float var = block_sum(d0 * d0 + d1 * d1, sm) * (1.f / Dm);
    float inv = rsqrtf(var + EPSv);
    out[row * Dm + t]        = d0 * inv * g[t]        + be[t];
    out[row * Dm + t + 256]  = d1 * inv * g[t + 256]  + be[t + 256];
}

// ---------------- launch ----------------
extern "C" void kernel_launch(void* const* d_in, const int* in_sizes, int n_in,
                              void* d_out, int out_size)
{
    const float* x    = (const float*)d_in[0];
    const float* Wq   = (const float*)d_in[1];
    const float* bq   = (const float*)d_in[2];
    const float* Wk   = (const float*)d_in[3];
    const float* bk   = (const float*)d_in[4];
    const float* Wv   = (const float*)d_in[5];
    const float* bv   = (const float*)d_in[6];
    const float* Wo   = (const float*)d_in[7];
    const float* bo   = (const float*)d_in[8];
    const float* ln1g = (const float*)d_in[9];
    const float* ln1b = (const float*)d_in[10];
    const float* W1   = (const float*)d_in[11];
    const float* b1   = (const float*)d_in[12];
    const float* W2   = (const float*)d_in[13];
    const float* b2   = (const float*)d_in[14];
    const float* ln2g = (const float*)d_in[15];
    const float* ln2b = (const float*)d_in[16];
    float* out = (float*)d_out;

    float *pq, *pk, *pv, *ps, *pc, *pmha, *py1, *pf1, *pf2;
    cudaGetSymbolAddress((void**)&pq, g_q);
    cudaGetSymbolAddress((void**)&pk, g_k);
    cudaGetSymbolAddress((void**)&pv, g_v);
    cudaGetSymbolAddress((void**)&ps, g_s);
    cudaGetSymbolAddress((void**)&pc, g_concat);
    cudaGetSymbolAddress((void**)&pmha, g_mha);
    cudaGetSymbolAddress((void**)&py1, g_y1);
    cudaGetSymbolAddress((void**)&pf1, g_ff1);
    cudaGetSymbolAddress((void**)&pf2, g_ff2);

    const float inv_sqrt_d = 0.044194173824159216f; // 1/sqrt(512)

    // 1) Q/K/V projections: per-head [8192,512] = x[8192,512] @ W[h][512,512] + b[h]
    {
        dim3 grid(Dm / BNt, BT / BMt, HH);
        gemm_kernel<0><<<grid, 256>>>(x, Wq, bq, pq, Dm, Dm, Dm, Dm,
                                      0L, (long)Dm * Dm, (long)Dm,
                                      1, (long)BT * Dm, 0L, 1.f);
        gemm_kernel<0><<<grid, 256>>>(x, Wk, bk, pk, Dm, Dm, Dm, Dm,
                                      0L, (long)Dm * Dm, (long)Dm,
                                      1, (long)BT * Dm, 0L, 1.f);
        gemm_kernel<0><<<grid, 256>>>(x, Wv, bv, pv, Dm, Dm, Dm, Dm,
                                      0L, (long)Dm * Dm, (long)Dm,
                                      1, (long)BT * Dm, 0L, 1.f);
    }

    // 2) scores[h,b] = Q[h,b] @ K[h,b]^T * (1/sqrt(D))   (batch z = h*B+b)
    {
        dim3 grid(TT / BNt, TT / BMt, HH * BB);
        gemm_kernel<1><<<grid, 256>>>(pq, pk, nullptr, ps, Dm, Dm, Dm, TT,
                                      (long)TT * Dm, (long)TT * Dm, 0L,
                                      1, (long)TT * TT, 0L, inv_sqrt_d);
    }

    // 3) row softmax over 64*1024 rows of length 1024
    softmax_kernel<<<HH * BB * TT, 256>>>(ps);

    // 4) attn @ V, written directly into concat layout [B*T, H*D]
    //    C offset: col h*512, row block b*1024 (ldc = H*D = 4096)
    {
        dim3 grid(Dm / BNt, TT / BMt, HH * BB);
        gemm_kernel<0><<<grid, 256>>>(ps, pv, nullptr, pc, TT, TT, Dm, HH * Dm,
                                      (long)TT * TT, (long)TT * Dm, 0L,
                                      BB, (long)Dm, (long)TT * HH * Dm, 1.f);
    }

    // 5) output projection: [8192,4096] @ Wo[4096,512] + bo
    {
        dim3 grid(Dm / BNt, BT / BMt, 1);
        gemm_kernel<0><<<grid, 256>>>(pc, Wo, bo, pmha, HH * Dm, HH * Dm, Dm, Dm,
                                      0L, 0L, 0L, 1, 0L, 0L, 1.f);
    }

    // 6) y1 = LN(mha + x)
    add_ln_kernel<0><<<BT, 256>>>(pmha, x, ln1g, ln1b, py1);

    // 7) FFN1: [8192,512] @ W1[512,2048] + b1
    {
        dim3 grid(DFFm / BNt, BT / BMt, 1);
        gemm_kernel<0><<<grid, 256>>>(py1, W1, b1, pf1, Dm, Dm, DFFm, DFFm,
                                      0L, 0L, 0L, 1, 0L, 0L, 1.f);
    }

    // 8) FFN2: [8192,2048] @ W2[2048,512] + b2
    {
        dim3 grid(Dm / BNt, BT / BMt, 1);
        gemm_kernel<0><<<grid, 256>>>(pf1, W2, b2, pf2, DFFm, DFFm, Dm, Dm,
                                      0L, 0L, 0L, 1, 0L, 0L, 1.f);
    }

    // 9) out = LN(relu(ff2) + y1)
    add_ln_kernel<1><<<BT, 256>>>(pf2, py1, ln2g, ln2b, out);
}

// round 7
// speedup vs baseline: 2.1268x; 2.1268x over previous
#include <cuda_runtime.h>
#include <cuda_bf16.h>
#include <math.h>
#include <cstdint>

#define HH   8
#define Dm   512
#define DFFm 2048
#define BB   8
#define TT   1024
#define BT   (BB*TT)
#define EPSv 1e-5f

typedef __nv_bfloat16 bf16;

// ---------------- scratch (static __device__, allocation-free) ----------------
__device__ bf16 g_xh[BT*Dm], g_xl[BT*Dm];
__device__ bf16 g_WqTh[HH*Dm*Dm], g_WqTl[HH*Dm*Dm];
__device__ bf16 g_WkTh[HH*Dm*Dm], g_WkTl[HH*Dm*Dm];
__device__ bf16 g_WvTh[HH*Dm*Dm], g_WvTl[HH*Dm*Dm];
__device__ bf16 g_WoTh[Dm*HH*Dm], g_WoTl[Dm*HH*Dm];
__device__ bf16 g_W1Th[DFFm*Dm], g_W1Tl[DFFm*Dm];
__device__ bf16 g_W2Th[Dm*DFFm], g_W2Tl[Dm*DFFm];
__device__ bf16 g_qh[HH*BT*Dm], g_ql[HH*BT*Dm];
__device__ bf16 g_kh[HH*BT*Dm], g_kl[HH*BT*Dm];
__device__ bf16 g_vth[HH*BT*Dm], g_vtl[HH*BT*Dm];          // [H,B,D,T] transposed
__device__ float g_s[(size_t)HH*BB*TT*TT];                  // 256 MB scores
__device__ bf16 g_ph[(size_t)HH*BB*TT*TT], g_pl[(size_t)HH*BB*TT*TT];
__device__ bf16 g_ch[(size_t)BT*HH*Dm], g_cl[(size_t)BT*HH*Dm];  // concat planes
__device__ float g_mha[BT*Dm];
__device__ float g_y1[BT*Dm];
__device__ bf16 g_y1h[BT*Dm], g_y1l[BT*Dm];
__device__ bf16 g_f1h[BT*DFFm], g_f1l[BT*DFFm];
__device__ float g_ff2[BT*Dm];

// ---------------- helpers ----------------
__device__ __forceinline__ uint32_t smem_u32(const void* p) {
    uint32_t a;
    asm("{ .reg .u64 t; cvta.to.shared.u64 t, %1; cvt.u32.u64 %0, t; }" : "=r"(a) : "l"(p));
    return a;
}

#define CPASYNC16(sa, ga) \
    asm volatile("cp.async.ca.shared.global [%0], [%1], 16;" :: "r"(sa), "l"(ga) : "memory")
#define CP_COMMIT() asm volatile("cp.async.commit_group;" ::: "memory")
#define CP_WAIT1()  asm volatile("cp.async.wait_group 1;" ::: "memory")
#define CP_WAIT0()  asm volatile("cp.async.wait_group 0;" ::: "memory")

#define LDSM4(r, addr) \
    asm volatile("ldmatrix.sync.aligned.m8n8.x4.shared.b16 {%0,%1,%2,%3}, [%4];" \
        : "=r"((r)[0]), "=r"((r)[1]), "=r"((r)[2]), "=r"((r)[3]) : "r"(addr))

__device__ __forceinline__ void mma16816(float* c, const uint32_t* a, const uint32_t* b) {
    asm volatile("mma.sync.aligned.m16n8k16.row.col.f32.bf16.bf16.f32 "
        "{%0,%1,%2,%3}, {%4,%5,%6,%7}, {%8,%9}, {%0,%1,%2,%3};"
        : "+f"(c[0]), "+f"(c[1]), "+f"(c[2]), "+f"(c[3])
        : "r"(a[0]), "r"(a[1]), "r"(a[2]), "r"(a[3]), "r"(b[0]), "r"(b[1]));
}

// ============ universal bf16x3 mma.sync GEMM: C = alpha*(A @ B^T) + bias ============
// A planes [M,K] K-major (lda), B planes [N,K] K-major (ldb).
// EPI: 1 = write fp32 C, 2 = write bf16 hi/lo planes, 4 = transposed V write [H,B,D,T]
// smem: 2 stages x 4 planes x 128 rows x 24 bf16 (48B padded rows) = 49152 B
#define STAGE_BYTES 24576
#define PLANE_BYTES 6144
#define ROW_BYTES   48
#define SMEM_BYTES  49152

template<int EPI>
__global__ void __launch_bounds__(256)
gemm_mma(const bf16* __restrict__ Ah, const bf16* __restrict__ Al,
         const bf16* __restrict__ Bh, const bf16* __restrict__ Bl,
         const float* __restrict__ bias,
         float* __restrict__ Cf, bf16* __restrict__ Ch, bf16* __restrict__ Cl,
         int K, int lda, int ldb, int ldc,
         long sA, long sB, long sBias,
         int innerB, long sC_outer, long sC_inner, float alpha)
{
    extern __shared__ char smem[];
    const uint32_t sb = smem_u32(smem);

    const int tid = threadIdx.x, lane = tid & 31, wid = tid >> 5;
    const int wm = wid >> 2, wn = wid & 3;
    const int z = blockIdx.z;

    const bf16* Abh = Ah + (long)z * sA;
    const bf16* Abl = Al + (long)z * sA;
    const bf16* Bbh = Bh + (long)z * sB;
    const bf16* Bbl = Bl + (long)z * sB;
    const float* biasb = bias ? (bias + (long)z * sBias) : nullptr;
    long coff = (innerB > 1) ? (long)(z / innerB) * sC_outer + (long)(z % innerB) * sC_inner
                             : (long)z * sC_outer;

    const int mBase = blockIdx.y * 128;
    const int nBase = blockIdx.x * 128;

    // loader: each thread copies one 16B chunk per plane per stage
    const int lrow = tid >> 1;                 // 0..127
    const int lco  = (tid & 1) * 8;            // element col offset
    const uint32_t ssub = (uint32_t)lrow * ROW_BYTES + (tid & 1) * 16;
    const long gA = (long)(mBase + lrow) * lda + lco;
    const long gB = (long)(nBase + lrow) * ldb + lco;

    float acc[4][4][4];
    #pragma unroll
    for (int i = 0; i < 4; i++)
        #pragma unroll
        for (int j = 0; j < 4; j++)
            #pragma unroll
            for (int r = 0; r < 4; r++) acc[i][j][r] = 0.f;

    const int nStages = K >> 4;

    // prefetch stage 0
    {
        uint32_t base = sb;
        CPASYNC16(base + ssub,                   (const char*)(Abh + gA));
        CPASYNC16(base + PLANE_BYTES + ssub,     (const char*)(Abl + gA));
        CPASYNC16(base + 2*PLANE_BYTES + ssub,   (const char*)(Bbh + gB));
        CPASYNC16(base + 3*PLANE_BYTES + ssub,   (const char*)(Bbl + gB));
        CP_COMMIT();
    }

    // lane maps for ldmatrix
    const uint32_t aoff = (uint32_t)(lane & 15) * ROW_BYTES + (lane >> 4) * 16;
    const int nrow  = (lane & 7) + ((lane >> 4) << 3);
    const int khalf = (lane >> 3) & 1;
    const uint32_t boff = (uint32_t)nrow * ROW_BYTES + khalf * 16;

    for (int s = 0; s < nStages; s++) {
        if (s + 1 < nStages) {
            uint32_t base = sb + ((s + 1) & 1) * STAGE_BYTES;
            long k0 = (long)(s + 1) << 4;
            CPASYNC16(base + ssub,                 (const char*)(Abh + gA + k0));
            CPASYNC16(base + PLANE_BYTES + ssub,   (const char*)(Abl + gA + k0));
            CPASYNC16(base + 2*PLANE_BYTES + ssub, (const char*)(Bbh + gB + k0));
            CPASYNC16(base + 3*PLANE_BYTES + ssub, (const char*)(Bbl + gB + k0));
            CP_COMMIT();
            CP_WAIT1();
        } else {
            CP_WAIT0();
        }
        __syncthreads();

        const uint32_t base = sb + (s & 1) * STAGE_BYTES;
        uint32_t ah[4][4], al[4][4];
        #pragma unroll
        for (int mi = 0; mi < 4; mi++) {
            uint32_t o = base + (uint32_t)(wm * 64 + mi * 16) * ROW_BYTES + aoff;
            LDSM4(ah[mi], o);
            LDSM4(al[mi], o + PLANE_BYTES);
        }
        uint32_t bh[2][4], bl[2][4];
        #pragma unroll
        for (int p = 0; p < 2; p++) {
            uint32_t o = base + 2*PLANE_BYTES + (uint32_t)(wn * 32 + p * 16) * ROW_BYTES + boff;
            LDSM4(bh[p], o);
            LDSM4(bl[p], o + PLANE_BYTES);
        }
        #pragma unroll
        for (int mi = 0; mi < 4; mi++)
            #pragma unroll
            for (int p = 0; p < 2; p++)
                #pragma unroll
                for (int s2 = 0; s2 < 2; s2++) {
                    const int ni = p * 2 + s2;
                    mma16816(acc[mi][ni], ah[mi], &bh[p][s2 * 2]);
                    mma16816(acc[mi][ni], al[mi], &bh[p][s2 * 2]);
                    mma16816(acc[mi][ni], ah[mi], &bl[p][s2 * 2]);
                }
        __syncthreads();
    }

    // ---- epilogue: fragment layout m16n8: c0,c1 -> (row=lane/4, col=2(lane%4)+{0,1}); c2,c3 -> row+8
    const int er = mBase + wm * 64 + (lane >> 2);
    const int ec = nBase + wn * 32 + (lane & 3) * 2;

    #pragma unroll
    for (int mi = 0; mi < 4; mi++) {
        #pragma unroll
        for (int ni = 0; ni < 4; ni++) {
            const int gc = ec + ni * 8;
            float b0 = 0.f, b1 = 0.f;
            if (biasb) { b0 = __ldg(&biasb[gc]); b1 = __ldg(&biasb[gc + 1]); }
            #pragma unroll
            for (int half = 0; half < 2; half++) {
                const int gr = er + mi * 16 + half * 8;
                float v0 = acc[mi][ni][half * 2 + 0] * alpha + b0;
                float v1 = acc[mi][ni][half * 2 + 1] * alpha + b1;
                if (EPI == 4) {
                    // transposed V: out[h][b][d][t], z = h, gr = b*T + t, gc = d
                    const long zb = (long)z * ((long)BB * Dm * TT)
                                  + (long)(gr >> 10) * ((long)Dm * TT);
                    const long t = gr & 1023;
                    long a0 = zb + (long)gc * TT + t;
                    long a1 = zb + (long)(gc + 1) * TT + t;
                    bf16 h0 = __float2bfloat16_rn(v0);
                    bf16 h1 = __float2bfloat16_rn(v1);
                    Ch[a0] = h0; Cl[a0] = __float2bfloat16_rn(v0 - __bfloat162float(h0));
                    Ch[a1] = h1; Cl[a1] = __float2bfloat16_rn(v1 - __bfloat162float(h1));
                } else {
                    const long baseo = coff + (long)gr * ldc + gc;
                    if (EPI & 1) {
                        float2 f; f.x = v0; f.y = v1;
                        *(float2*)(Cf + baseo) = f;
                    }
                    if (EPI & 2) {
                        bf16 h0 = __float2bfloat16_rn(v0);
                        bf16 h1 = __float2bfloat16_rn(v1);
                        bf16 l0 = __float2bfloat16_rn(v0 - __bfloat162float(h0));
                        bf16 l1 = __float2bfloat16_rn(v1 - __bfloat162float(h1));
                        uint16_t a16 = *(uint16_t*)&h0, b16v = *(uint16_t*)&h1;
                        uint16_t c16 = *(uint16_t*)&l0, d16 = *(uint16_t*)&l1;
                        *(uint32_t*)(Ch + baseo) = (uint32_t)a16 | ((uint32_t)b16v << 16);
                        *(uint32_t*)(Cl + baseo) = (uint32_t)c16 | ((uint32_t)d16 << 16);
                    }
                }
            }
        }
    }
}

// ---------------- transpose + split: out[c][r] = in[r][c] -> hi/lo planes ----------------
__global__ void __launch_bounds__(256)
tsplit(const float* __restrict__ in, bf16* __restrict__ oh, bf16* __restrict__ ol,
       int R, int C, long sIn, long sOut)
{
    __shared__ float t[32][33];
    in += (long)blockIdx.z * sIn;
    oh += (long)blockIdx.z * sOut;
    ol += (long)blockIdx.z * sOut;
    const int cb = blockIdx.x * 32, rb = blockIdx.y * 32;
    const int x = threadIdx.x & 31, y = threadIdx.x >> 5;
    #pragma unroll
    for (int i = 0; i < 32; i += 8)
        t[y + i][x] = in[(long)(rb + y + i) * C + cb + x];
    __syncthreads();
    #pragma unroll
    for (int i = 0; i < 32; i += 8) {
        float v = t[x][y + i];
        bf16 h = __float2bfloat16_rn(v);
        long o = (long)(cb + y + i) * R + rb + x;
        oh[o] = h;
        ol[o] = __float2bfloat16_rn(v - __bfloat162float(h));
    }
}

// ---------------- elementwise split ----------------
__global__ void __launch_bounds__(256)
esplit(const float* __restrict__ in, bf16* __restrict__ oh, bf16* __restrict__ ol, int n)
{
    int i = blockIdx.x * 256 + threadIdx.x;
    if (i < n) {
        float v = in[i];
        bf16 h = __float2bfloat16_rn(v);
        oh[i] = h;
        ol[i] = __float2bfloat16_rn(v - __bfloat162float(h));
    }
}

// ---------------- block reductions ----------------
__device__ __forceinline__ float block_sum(float v, float* sm) {
    #pragma unroll
    for (int o = 16; o; o >>= 1) v += __shfl_xor_sync(0xffffffffu, v, o);
    if ((threadIdx.x & 31) == 0) sm[threadIdx.x >> 5] = v;
    __syncthreads();
    if (threadIdx.x < 8) {
        float s = sm[threadIdx.x];
        #pragma unroll
        for (int o = 4; o; o >>= 1) s += __shfl_xor_sync(0xffu, s, o);
        if (threadIdx.x == 0) sm[0] = s;
    }
    __syncthreads();
    float r = sm[0];
    __syncthreads();
    return r;
}
__device__ __forceinline__ float block_max(float v, float* sm) {
    #pragma unroll
    for (int o = 16; o; o >>= 1) v = fmaxf(v, __shfl_xor_sync(0xffffffffu, v, o));
    if ((threadIdx.x & 31) == 0) sm[threadIdx.x >> 5] = v;
    __syncthreads();
    if (threadIdx.x < 8) {
        float s = sm[threadIdx.x];
        #pragma unroll
        for (int o = 4; o; o >>= 1) s = fmaxf(s, __shfl_xor_sync(0xffu, s, o));
        if (threadIdx.x == 0) sm[0] = s;
    }
    __syncthreads();
    float r = sm[0];
    __syncthreads();
    return r;
}

// ---------------- softmax: fp32 scores -> bf16 hi/lo probability planes ----------------
__global__ void __launch_bounds__(256)
softmax_kernel(const float* __restrict__ S, bf16* __restrict__ Ph, bf16* __restrict__ Pl)
{
    __shared__ float sm[8];
    const size_t base = (size_t)blockIdx.x * TT;
    const float* p = S + base;
    int t = threadIdx.x;
    float x0 = p[t], x1 = p[t + 256], x2 = p[t + 512], x3 = p[t + 768];
    float m = block_max(fmaxf(fmaxf(x0, x1), fmaxf(x2, x3)), sm);
    float e0 = __expf(x0 - m), e1 = __expf(x1 - m);
    float e2 = __expf(x2 - m), e3 = __expf(x3 - m);
    float s = block_sum(e0 + e1 + e2 + e3, sm);
    float inv = 1.f / s;
    #pragma unroll
    for (int q = 0; q < 4; q++) {
        float v = (q == 0 ? e0 : q == 1 ? e1 : q == 2 ? e2 : e3) * inv;
        bf16 h = __float2bfloat16_rn(v);
        size_t idx = base + t + q * 256;
        Ph[idx] = h;
        Pl[idx] = __float2bfloat16_rn(v - __bfloat162float(h));
    }
}

// ---------------- fused (relu) + residual + LayerNorm (+ optional bf16 planes) ----------------
template<int RELU, int HILO>
__global__ void __launch_bounds__(256)
add_ln_kernel(const float* __restrict__ a, const float* __restrict__ res,
              const float* __restrict__ g, const float* __restrict__ be,
              float* __restrict__ out, bf16* __restrict__ oh, bf16* __restrict__ ol)
{
    __shared__ float sm[8];
    long row = blockIdx.x;
    const float* ap = a + row * Dm;
    const float* rp = res + row * Dm;
    int t = threadIdx.x;
    float v0 = ap[t], v1 = ap[t + 256];
    if (RELU) { v0 = fmaxf(v0, 0.f); v1 = fmaxf(v1, 0.f); }
    v0 += rp[t]; v1 += rp[t + 256];
    float mean = block_sum(v0 + v1, sm) * (1.f / Dm);
    float d0 = v0 - mean, d1 = v1 - mean;
    float var = block_sum(d0 * d0 + d1 * d1, sm) * (1.f / Dm);
    float inv = rsqrtf(var + EPSv);
    float o0 = d0 * inv * g[t] + be[t];
    float o1 = d1 * inv * g[t + 256] + be[t + 256];
    out[row * Dm + t] = o0;
    out[row * Dm + t + 256] = o1;
    if (HILO) {
        bf16 h0 = __float2bfloat16_rn(o0), h1 = __float2bfloat16_rn(o1);
        oh[row * Dm + t] = h0;
        oh[row * Dm + t + 256] = h1;
        ol[row * Dm + t] = __float2bfloat16_rn(o0 - __bfloat162float(h0));
        ol[row * Dm + t + 256] = __float2bfloat16_rn(o1 - __bfloat162float(h1));
    }
}

// ---------------- launch ----------------
extern "C" void kernel_launch(void* const* d_in, const int* in_sizes, int n_in,
                              void* d_out, int out_size)
{
    const float* x    = (const float*)d_in[0];
    const float* Wq   = (const float*)d_in[1];
    const float* bq   = (const float*)d_in[2];
    const float* Wk   = (const float*)d_in[3];
    const float* bk   = (const float*)d_in[4];
    const float* Wv   = (const float*)d_in[5];
    const float* bv   = (const float*)d_in[6];
    const float* Wo   = (const float*)d_in[7];
    const float* bo   = (const float*)d_in[8];
    const float* ln1g = (const float*)d_in[9];
    const float* ln1b = (const float*)d_in[10];
    const float* W1   = (const float*)d_in[11];
    const float* b1   = (const float*)d_in[12];
    const float* W2   = (const float*)d_in[13];
    const float* b2   = (const float*)d_in[14];
    const float* ln2g = (const float*)d_in[15];
    const float* ln2b = (const float*)d_in[16];
    float* out = (float*)d_out;

    bf16 *xh, *xl, *WqTh, *WqTl, *WkTh, *WkTl, *WvTh, *WvTl;
    bf16 *WoTh, *WoTl, *W1Th, *W1Tl, *W2Th, *W2Tl;
    bf16 *qh, *ql, *kh, *kl, *vth, *vtl, *ph, *pl, *chp, *clp, *y1h, *y1l, *f1h, *f1l;
    float *ps, *pmha, *py1, *pff2;
    cudaGetSymbolAddress((void**)&xh, g_xh);   cudaGetSymbolAddress((void**)&xl, g_xl);
    cudaGetSymbolAddress((void**)&WqTh, g_WqTh); cudaGetSymbolAddress((void**)&WqTl, g_WqTl);
    cudaGetSymbolAddress((void**)&WkTh, g_WkTh); cudaGetSymbolAddress((void**)&WkTl, g_WkTl);
    cudaGetSymbolAddress((void**)&WvTh, g_WvTh); cudaGetSymbolAddress((void**)&WvTl, g_WvTl);
    cudaGetSymbolAddress((void**)&WoTh, g_WoTh); cudaGetSymbolAddress((void**)&WoTl, g_WoTl);
    cudaGetSymbolAddress((void**)&W1Th, g_W1Th); cudaGetSymbolAddress((void**)&W1Tl, g_W1Tl);
    cudaGetSymbolAddress((void**)&W2Th, g_W2Th); cudaGetSymbolAddress((void**)&W2Tl, g_W2Tl);
    cudaGetSymbolAddress((void**)&qh, g_qh);   cudaGetSymbolAddress((void**)&ql, g_ql);
    cudaGetSymbolAddress((void**)&kh, g_kh);   cudaGetSymbolAddress((void**)&kl, g_kl);
    cudaGetSymbolAddress((void**)&vth, g_vth); cudaGetSymbolAddress((void**)&vtl, g_vtl);
    cudaGetSymbolAddress((void**)&ps, g_s);
    cudaGetSymbolAddress((void**)&ph, g_ph);   cudaGetSymbolAddress((void**)&pl, g_pl);
    cudaGetSymbolAddress((void**)&chp, g_ch);  cudaGetSymbolAddress((void**)&clp, g_cl);
    cudaGetSymbolAddress((void**)&pmha, g_mha);
    cudaGetSymbolAddress((void**)&py1, g_y1);
    cudaGetSymbolAddress((void**)&y1h, g_y1h); cudaGetSymbolAddress((void**)&y1l, g_y1l);
    cudaGetSymbolAddress((void**)&f1h, g_f1h); cudaGetSymbolAddress((void**)&f1l, g_f1l);
    cudaGetSymbolAddress((void**)&pff2, g_ff2);

    const float inv_sqrt_d = 0.044194173824159216f;

    // ---- operand prep: splits + transposed weight planes ----
    esplit<<<(BT * Dm + 255) / 256, 256>>>(x, xh, xl, BT * Dm);
    tsplit<<<dim3(Dm / 32, Dm / 32, HH), 256>>>(Wq, WqTh, WqTl, Dm, Dm, (long)Dm * Dm, (long)Dm * Dm);
    tsplit<<<dim3(Dm / 32, Dm / 32, HH), 256>>>(Wk, WkTh, WkTl, Dm, Dm, (long)Dm * Dm, (long)Dm * Dm);
    tsplit<<<dim3(Dm / 32, Dm / 32, HH), 256>>>(Wv, WvTh, WvTl, Dm, Dm, (long)Dm * Dm, (long)Dm * Dm);
    tsplit<<<dim3(Dm / 32, (HH * Dm) / 32, 1), 256>>>(Wo, WoTh, WoTl, HH * Dm, Dm, 0L, 0L);
    tsplit<<<dim3(DFFm / 32, Dm / 32, 1), 256>>>(W1, W1Th, W1Tl, Dm, DFFm, 0L, 0L);
    tsplit<<<dim3(Dm / 32, DFFm / 32, 1), 256>>>(W2, W2Th, W2Tl, DFFm, Dm, 0L, 0L);

    // ---- Q/K projections -> hi/lo planes [H, B*T, D]; V -> transposed [H,B,D,T] ----
    {
        dim3 grid(Dm / 128, BT / 128, HH);
        gemm_mma<2><<<grid, 256, SMEM_BYTES>>>(xh, xl, WqTh, WqTl, bq, nullptr, qh, ql,
            Dm, Dm, Dm, Dm, 0L, (long)Dm * Dm, (long)Dm, 1, (long)BT * Dm, 0L, 1.f);
        gemm_mma<2><<<grid, 256, SMEM_BYTES>>>(xh, xl, WkTh, WkTl, bk, nullptr, kh, kl,
            Dm, Dm, Dm, Dm, 0L, (long)Dm * Dm, (long)Dm, 1, (long)BT * Dm, 0L, 1.f);
        gemm_mma<4><<<grid, 256, SMEM_BYTES>>>(xh, xl, WvTh, WvTl, bv, nullptr, vth, vtl,
            Dm, Dm, Dm, 0, 0L, (long)Dm * Dm, (long)Dm, 1, 0L, 0L, 1.f);
    }

    // ---- scores = Q @ K^T * 1/sqrt(D), fp32 out ----
    {
        dim3 grid(TT / 128, TT / 128, HH * BB);
        gemm_mma<1><<<grid, 256, SMEM_BYTES>>>(qh, ql, kh, kl, nullptr, ps, nullptr, nullptr,
            Dm, Dm, Dm, TT, (long)TT * Dm, (long)TT * Dm, 0L, 1, (long)TT * TT, 0L, inv_sqrt_d);
    }

    // ---- softmax -> P hi/lo planes ----
    softmax_kernel<<<HH * BB * TT, 256>>>(ps, ph, pl);

    // ---- attn @ V -> concat planes [B*T, H*D] ----
    {
        dim3 grid(Dm / 128, TT / 128, HH * BB);
        gemm_mma<2><<<grid, 256, SMEM_BYTES>>>(ph, pl, vth, vtl, nullptr, nullptr, chp, clp,
            TT, TT, TT, HH * Dm, (long)TT * TT, (long)Dm * TT, 0L,
            BB, (long)Dm, (long)TT * HH * Dm, 1.f);
    }

    // ---- output projection -> mha fp32 ----
    {
        dim3 grid(Dm / 128, BT / 128, 1);
        gemm_mma<1><<<grid, 256, SMEM_BYTES>>>(chp, clp, WoTh, WoTl, bo, pmha, nullptr, nullptr,
            HH * Dm, HH * Dm, HH * Dm, Dm, 0L, 0L, 0L, 1, 0L, 0L, 1.f);
    }

    // ---- y1 = LN(mha + x), fp32 + planes ----
    add_ln_kernel<0, 1><<<BT, 256>>>(pmha, x, ln1g, ln1b, py1, y1h, y1l);

    // ---- FFN1 -> f1 planes ----
    {
        dim3 grid(DFFm / 128, BT / 128, 1);
        gemm_mma<2><<<grid, 256, SMEM_BYTES>>>(y1h, y1l, W1Th, W1Tl, b1, nullptr, f1h, f1l,
            Dm, Dm, Dm, DFFm, 0L, 0L, 0L, 1, 0L, 0L, 1.f);
    }

    // ---- FFN2 -> ff2 fp32 ----
    {
        dim3 grid(Dm / 128, BT / 128, 1);
        gemm_mma<1><<<grid, 256, SMEM_BYTES>>>(f1h, f1l, W2Th, W2Tl, b2, pff2, nullptr, nullptr,
            DFFm, DFFm, DFFm, Dm, 0L, 0L, 0L, 1, 0L, 0L, 1.f);
    }

    // ---- out = LN(relu(ff2) + y1) ----
    add_ln_kernel<1, 0><<<BT, 256>>>(pff2, py1, ln2g, ln2b, out, nullptr, nullptr);
}

// round 8
// speedup vs baseline: 2.5674x; 1.2072x over previous
#include <cuda_runtime.h>
#include <cuda_bf16.h>
#include <math.h>
#include <cstdint>

#define HH   8
#define Dm   512
#define DFFm 2048
#define BB   8
#define TT   1024
#define BT   (BB*TT)
#define EPSv 1e-5f

typedef __nv_bfloat16 bf16;

// ---------------- scratch (static __device__, allocation-free) ----------------
__device__ bf16 g_xh[BT*Dm], g_xl[BT*Dm];
__device__ bf16 g_Wqh[HH*Dm*Dm], g_Wql[HH*Dm*Dm];
__device__ bf16 g_Wkh[HH*Dm*Dm], g_Wkl[HH*Dm*Dm];
__device__ bf16 g_Wvh[HH*Dm*Dm], g_Wvl[HH*Dm*Dm];
__device__ bf16 g_WoTh[Dm*HH*Dm], g_WoTl[Dm*HH*Dm];
__device__ bf16 g_W1Th[DFFm*Dm], g_W1Tl[DFFm*Dm];
__device__ bf16 g_W2Th[Dm*DFFm], g_W2Tl[Dm*DFFm];
__device__ bf16 g_Mth[HH*Dm*Dm], g_Mtl[HH*Dm*Dm];   // Mt[h][d'][d] = M_h[d,d']^T
__device__ bf16 g_Nth[HH*Dm*Dm], g_Ntl[HH*Dm*Dm];   // Nt[h][e][d]  = N_h[d,e]^T
__device__ float g_w0[HH*Dm];                        // Wk_h @ bq_h
__device__ float g_ccp[HH*Dm];                       // per-head bv_h @ Wo_h
__device__ bf16 g_uh[HH*BT*Dm], g_ul[HH*BT*Dm];      // u = x*M + w0
__device__ bf16 g_zth[HH*BT*Dm], g_ztl[HH*BT*Dm];    // z^T  [H,B,D,T]
__device__ float g_s[(size_t)HH*BB*TT*TT];           // 256 MB scores
__device__ bf16 g_ph[(size_t)HH*BB*TT*TT], g_pl[(size_t)HH*BB*TT*TT];
__device__ float g_parts[(size_t)HH*BT*Dm];          // per-head attn*z partials (fp32)
__device__ float g_y1[BT*Dm];
__device__ bf16 g_y1h[BT*Dm], g_y1l[BT*Dm];
__device__ bf16 g_f1h[BT*DFFm], g_f1l[BT*DFFm];
__device__ float g_ff2[BT*Dm];

// ---------------- helpers ----------------
__device__ __forceinline__ uint32_t smem_u32(const void* p) {
    uint32_t a;
    asm("{ .reg .u64 t; cvta.to.shared.u64 t, %1; cvt.u32.u64 %0, t; }" : "=r"(a) : "l"(p));
    return a;
}

#define CPASYNC16(sa, ga) \
    asm volatile("cp.async.ca.shared.global [%0], [%1], 16;" :: "r"(sa), "l"(ga) : "memory")
#define CP_COMMIT() asm volatile("cp.async.commit_group;" ::: "memory")
#define CP_WAIT1()  asm volatile("cp.async.wait_group 1;" ::: "memory")
#define CP_WAIT0()  asm volatile("cp.async.wait_group 0;" ::: "memory")

#define LDSM4(r, addr) \
    asm volatile("ldmatrix.sync.aligned.m8n8.x4.shared.b16 {%0,%1,%2,%3}, [%4];" \
        : "=r"((r)[0]), "=r"((r)[1]), "=r"((r)[2]), "=r"((r)[3]) : "r"(addr))

__device__ __forceinline__ void mma16816(float* c, const uint32_t* a, const uint32_t* b) {
    asm volatile("mma.sync.aligned.m16n8k16.row.col.f32.bf16.bf16.f32 "
        "{%0,%1,%2,%3}, {%4,%5,%6,%7}, {%8,%9}, {%0,%1,%2,%3};"
        : "+f"(c[0]), "+f"(c[1]), "+f"(c[2]), "+f"(c[3])
        : "r"(a[0]), "r"(a[1]), "r"(a[2]), "r"(a[3]), "r"(b[0]), "r"(b[1]));
}

// ============ universal bf16x3 mma.sync GEMM: C = alpha*(A @ B^T) + bias ============
// A planes [M,K] K-major (lda), B planes [N,K] K-major (ldb).
// B batch offset = ((modB>0) ? z%modB : z) * sB.
// EPI: 1 = write fp32 C, 2 = write bf16 hi/lo planes, 4 = transposed write [z,B,D,T]
#define STAGE_BYTES 24576
#define PLANE_BYTES 6144
#define ROW_BYTES   48
#define SMEM_BYTES  49152

template<int EPI>
__global__ void __launch_bounds__(256)
gemm_mma(const bf16* __restrict__ Ah, const bf16* __restrict__ Al,
         const bf16* __restrict__ Bh, const bf16* __restrict__ Bl,
         const float* __restrict__ bias,
         float* __restrict__ Cf, bf16* __restrict__ Ch, bf16* __restrict__ Cl,
         int K, int lda, int ldb, int ldc,
         long sA, long sB, int modB, long sBias,
         int innerB, long sC_outer, long sC_inner, float alpha)
{
    extern __shared__ char smem[];
    const uint32_t sb = smem_u32(smem);

    const int tid = threadIdx.x, lane = tid & 31, wid = tid >> 5;
    const int wm = wid >> 2, wn = wid & 3;
    const int z = blockIdx.z;

    const bf16* Abh = Ah + (long)z * sA;
    const bf16* Abl = Al + (long)z * sA;
    const long bOff = (modB > 0 ? (long)(z % modB) : (long)z) * sB;
    const bf16* Bbh = Bh + bOff;
    const bf16* Bbl = Bl + bOff;
    const float* biasb = bias ? (bias + (long)z * sBias) : nullptr;
    long coff = (innerB > 1) ? (long)(z / innerB) * sC_outer + (long)(z % innerB) * sC_inner
                             : (long)z * sC_outer;

    const int mBase = blockIdx.y * 128;
    const int nBase = blockIdx.x * 128;

    const int lrow = tid >> 1;
    const int lco  = (tid & 1) * 8;
    const uint32_t ssub = (uint32_t)lrow * ROW_BYTES + (tid & 1) * 16;
    const long gA = (long)(mBase + lrow) * lda + lco;
    const long gB = (long)(nBase + lrow) * ldb + lco;

    float acc[4][4][4];
    #pragma unroll
    for (int i = 0; i < 4; i++)
        #pragma unroll
        for (int j = 0; j < 4; j++)
            #pragma unroll
            for (int r = 0; r < 4; r++) acc[i][j][r] = 0.f;

    const int nStages = K >> 4;

    {
        uint32_t base = sb;
        CPASYNC16(base + ssub,                   (const char*)(Abh + gA));
        CPASYNC16(base + PLANE_BYTES + ssub,     (const char*)(Abl + gA));
        CPASYNC16(base + 2*PLANE_BYTES + ssub,   (const char*)(Bbh + gB));
        CPASYNC16(base + 3*PLANE_BYTES + ssub,   (const char*)(Bbl + gB));
        CP_COMMIT();
    }

    const uint32_t aoff = (uint32_t)(lane & 15) * ROW_BYTES + (lane >> 4) * 16;
    const int nrow  = (lane & 7) + ((lane >> 4) << 3);
    const int khalf = (lane >> 3) & 1;
    const uint32_t boff = (uint32_t)nrow * ROW_BYTES + khalf * 16;

    for (int s = 0; s < nStages; s++) {
        if (s + 1 < nStages) {
            uint32_t base = sb + ((s + 1) & 1) * STAGE_BYTES;
            long k0 = (long)(s + 1) << 4;
            CPASYNC16(base + ssub,                 (const char*)(Abh + gA + k0));
            CPASYNC16(base + PLANE_BYTES + ssub,   (const char*)(Abl + gA + k0));
            CPASYNC16(base + 2*PLANE_BYTES + ssub, (const char*)(Bbh + gB + k0));
            CPASYNC16(base + 3*PLANE_BYTES + ssub, (const char*)(Bbl + gB + k0));
            CP_COMMIT();
            CP_WAIT1();
        } else {
            CP_WAIT0();
        }
        __syncthreads();

        const uint32_t base = sb + (s & 1) * STAGE_BYTES;
        uint32_t ah[4][4], al[4][4];
        #pragma unroll
        for (int mi = 0; mi < 4; mi++) {
            uint32_t o = base + (uint32_t)(wm * 64 + mi * 16) * ROW_BYTES + aoff;
            LDSM4(ah[mi], o);
            LDSM4(al[mi], o + PLANE_BYTES);
        }
        uint32_t bh[2][4], bl[2][4];
        #pragma unroll
        for (int p = 0; p < 2; p++) {
            uint32_t o = base + 2*PLANE_BYTES + (uint32_t)(wn * 32 + p * 16) * ROW_BYTES + boff;
            LDSM4(bh[p], o);
            LDSM4(bl[p], o + PLANE_BYTES);
        }
        #pragma unroll
        for (int mi = 0; mi < 4; mi++)
            #pragma unroll
            for (int p = 0; p < 2; p++)
                #pragma unroll
                for (int s2 = 0; s2 < 2; s2++) {
                    const int ni = p * 2 + s2;
                    mma16816(acc[mi][ni], ah[mi], &bh[p][s2 * 2]);
                    mma16816(acc[mi][ni], al[mi], &bh[p][s2 * 2]);
                    mma16816(acc[mi][ni], ah[mi], &bl[p][s2 * 2]);
                }
        __syncthreads();
    }

    const int er = mBase + wm * 64 + (lane >> 2);
    const int ec = nBase + wn * 32 + (lane & 3) * 2;

    #pragma unroll
    for (int mi = 0; mi < 4; mi++) {
        #pragma unroll
        for (int ni = 0; ni < 4; ni++) {
            const int gc = ec + ni * 8;
            float b0 = 0.f, b1 = 0.f;
            if (biasb) { b0 = __ldg(&biasb[gc]); b1 = __ldg(&biasb[gc + 1]); }
            #pragma unroll
            for (int half = 0; half < 2; half++) {
                const int gr = er + mi * 16 + half * 8;
                float v0 = acc[mi][ni][half * 2 + 0] * alpha + b0;
                float v1 = acc[mi][ni][half * 2 + 1] * alpha + b1;
                if (EPI == 4) {
                    const long zb = (long)z * ((long)BB * Dm * TT)
                                  + (long)(gr >> 10) * ((long)Dm * TT);
                    const long t = gr & 1023;
                    long a0 = zb + (long)gc * TT + t;
                    long a1 = zb + (long)(gc + 1) * TT + t;
                    bf16 h0 = __float2bfloat16_rn(v0);
                    bf16 h1 = __float2bfloat16_rn(v1);
                    Ch[a0] = h0; Cl[a0] = __float2bfloat16_rn(v0 - __bfloat162float(h0));
                    Ch[a1] = h1; Cl[a1] = __float2bfloat16_rn(v1 - __bfloat162float(h1));
                } else {
                    const long baseo = coff + (long)gr * ldc + gc;
                    if (EPI & 1) {
                        float2 f; f.x = v0; f.y = v1;
                        *(float2*)(Cf + baseo) = f;
                    }
                    if (EPI & 2) {
                        bf16 h0 = __float2bfloat16_rn(v0);
                        bf16 h1 = __float2bfloat16_rn(v1);
                        bf16 l0 = __float2bfloat16_rn(v0 - __bfloat162float(h0));
                        bf16 l1 = __float2bfloat16_rn(v1 - __bfloat162float(h1));
                        uint16_t a16 = *(uint16_t*)&h0, b16v = *(uint16_t*)&h1;
                        uint16_t c16 = *(uint16_t*)&l0, d16 = *(uint16_t*)&l1;
                        *(uint32_t*)(Ch + baseo) = (uint32_t)a16 | ((uint32_t)b16v << 16);
                        *(uint32_t*)(Cl + baseo) = (uint32_t)c16 | ((uint32_t)d16 << 16);
                    }
                }
            }
        }
    }
}

// ---------------- transpose + split ----------------
__global__ void __launch_bounds__(256)
tsplit(const float* __restrict__ in, bf16* __restrict__ oh, bf16* __restrict__ ol,
       int R, int C, long sIn, long sOut)
{
    __shared__ float t[32][33];
    in += (long)blockIdx.z * sIn;
    oh += (long)blockIdx.z * sOut;
    ol += (long)blockIdx.z * sOut;
    const int cb = blockIdx.x * 32, rb = blockIdx.y * 32;
    const int x = threadIdx.x & 31, y = threadIdx.x >> 5;
    #pragma unroll
    for (int i = 0; i < 32; i += 8)
        t[y + i][x] = in[(long)(rb + y + i) * C + cb + x];
    __syncthreads();
    #pragma unroll
    for (int i = 0; i < 32; i += 8) {
        float v = t[x][y + i];
        bf16 h = __float2bfloat16_rn(v);
        long o = (long)(cb + y + i) * R + rb + x;
        oh[o] = h;
        ol[o] = __float2bfloat16_rn(v - __bfloat162float(h));
    }
}

// ---------------- elementwise split ----------------
__global__ void __launch_bounds__(256)
esplit(const float* __restrict__ in, bf16* __restrict__ oh, bf16* __restrict__ ol, int n)
{
    int i = blockIdx.x * 256 + threadIdx.x;
    if (i < n) {
        float v = in[i];
        bf16 h = __float2bfloat16_rn(v);
        oh[i] = h;
        ol[i] = __float2bfloat16_rn(v - __bfloat162float(h));
    }
}

// ---------------- vecprep: w0[h,d] = Wk_h[d,:]·bq_h ; ccp[h,e] = bv_h·Wo_h[:,e] ----------------
__global__ void __launch_bounds__(256)
vecprep(const float* __restrict__ Wk, const float* __restrict__ bq,
        const float* __restrict__ Wo, const float* __restrict__ bv,
        float* __restrict__ w0, float* __restrict__ ccp)
{
    const int bb = blockIdx.x;
    if (bb < 512) {
        // 8 warps, each one (h,d) pair
        const int wid = threadIdx.x >> 5, lane = threadIdx.x & 31;
        const int idx = bb * 8 + wid;           // 0..4095
        const int h = idx >> 9, d = idx & 511;
        const float* wr = Wk + (long)h * Dm * Dm + (long)d * Dm;
        const float* bqr = bq + h * Dm;
        float s = 0.f;
        #pragma unroll
        for (int e = lane; e < Dm; e += 32) s += wr[e] * bqr[e];
        #pragma unroll
        for (int o = 16; o; o >>= 1) s += __shfl_xor_sync(0xffffffffu, s, o);
        if (lane == 0) w0[idx] = s;
    } else {
        const int h = bb - 512;                 // 0..7
        const int t = threadIdx.x;
        float s0 = 0.f, s1 = 0.f;
        const float* Woh = Wo + (long)h * Dm * Dm;
        const float* bvh = bv + h * Dm;
        for (int m = 0; m < Dm; m++) {
            float b = bvh[m];
            s0 += b * Woh[(long)m * Dm + t];
            s1 += b * Woh[(long)m * Dm + t + 256];
        }
        ccp[h * Dm + t] = s0;
        ccp[h * Dm + t + 256] = s1;
    }
}

// ---------------- block reductions ----------------
__device__ __forceinline__ float block_sum(float v, float* sm) {
    #pragma unroll
    for (int o = 16; o; o >>= 1) v += __shfl_xor_sync(0xffffffffu, v, o);
    if ((threadIdx.x & 31) == 0) sm[threadIdx.x >> 5] = v;
    __syncthreads();
    if (threadIdx.x < 8) {
        float s = sm[threadIdx.x];
        #pragma unroll
        for (int o = 4; o; o >>= 1) s += __shfl_xor_sync(0xffu, s, o);
        if (threadIdx.x == 0) sm[0] = s;
    }
    __syncthreads();
    float r = sm[0];
    __syncthreads();
    return r;
}
__device__ __forceinline__ float block_max(float v, float* sm) {
    #pragma unroll
    for (int o = 16; o; o >>= 1) v = fmaxf(v, __shfl_xor_sync(0xffffffffu, v, o));
    if ((threadIdx.x & 31) == 0) sm[threadIdx.x >> 5] = v;
    __syncthreads();
    if (threadIdx.x < 8) {
        float s = sm[threadIdx.x];
        #pragma unroll
        for (int o = 4; o; o >>= 1) s = fmaxf(s, __shfl_xor_sync(0xffu, s, o));
        if (threadIdx.x == 0) sm[0] = s;
    }
    __syncthreads();
    float r = sm[0];
    __syncthreads();
    return r;
}

// ---------------- softmax ----------------
__global__ void __launch_bounds__(256)
softmax_kernel(const float* __restrict__ S, bf16* __restrict__ Ph, bf16* __restrict__ Pl)
{
    __shared__ float sm[8];
    const size_t base = (size_t)blockIdx.x * TT;
    const float* p = S + base;
    int t = threadIdx.x;
    float x0 = p[t], x1 = p[t + 256], x2 = p[t + 512], x3 = p[t + 768];
    float m = block_max(fmaxf(fmaxf(x0, x1), fmaxf(x2, x3)), sm);
    float e0 = __expf(x0 - m), e1 = __expf(x1 - m);
    float e2 = __expf(x2 - m), e3 = __expf(x3 - m);
    float s = block_sum(e0 + e1 + e2 + e3, sm);
    float inv = 1.f / s;
    #pragma unroll
    for (int q = 0; q < 4; q++) {
        float v = (q == 0 ? e0 : q == 1 ? e1 : q == 2 ? e2 : e3) * inv;
        bf16 h = __float2bfloat16_rn(v);
        size_t idx = base + t + q * 256;
        Ph[idx] = h;
        Pl[idx] = __float2bfloat16_rn(v - __bfloat162float(h));
    }
}

// ---------------- reduce heads + cc + residual + LN1 -> y1 (fp32 + planes) ----------------
__global__ void __launch_bounds__(256)
reduce_ln1(const float* __restrict__ parts, const float* __restrict__ x,
           const float* __restrict__ ccp, const float* __restrict__ bo,
           const float* __restrict__ g, const float* __restrict__ be,
           float* __restrict__ out, bf16* __restrict__ oh, bf16* __restrict__ ol)
{
    __shared__ float sm[8];
    const long row = blockIdx.x;
    const long b = row >> 10, t0 = row & 1023;
    const int t = threadIdx.x;
    float v0, v1;
    {
        float c0 = bo[t], c1 = bo[t + 256];
        #pragma unroll
        for (int h = 0; h < HH; h++) {
            c0 += ccp[h * Dm + t];
            c1 += ccp[h * Dm + t + 256];
        }
        v0 = x[row * Dm + t] + c0;
        v1 = x[row * Dm + t + 256] + c1;
        #pragma unroll
        for (int h = 0; h < HH; h++) {
            const long pr = (((long)h * BB + b) * TT + t0) * Dm;
            v0 += parts[pr + t];
            v1 += parts[pr + t + 256];
        }
    }
    float mean = block_sum(v0 + v1, sm) * (1.f / Dm);
    float d0 = v0 - mean, d1 = v1 - mean;
    float var = block_sum(d0 * d0 + d1 * d1, sm) * (1.f / Dm);
    float inv = rsqrtf(var + EPSv);
    float o0 = d0 * inv * g[t] + be[t];
    float o1 = d1 * inv * g[t + 256] + be[t + 256];
    out[row * Dm + t] = o0;
    out[row * Dm + t + 256] = o1;
    bf16 h0 = __float2bfloat16_rn(o0), h1 = __float2bfloat16_rn(o1);
    oh[row * Dm + t] = h0;
    oh[row * Dm + t + 256] = h1;
    ol[row * Dm + t] = __float2bfloat16_rn(o0 - __bfloat162float(h0));
    ol[row * Dm + t + 256] = __float2bfloat16_rn(o1 - __bfloat162float(h1));
}

// ---------------- relu + residual + LN2 ----------------
__global__ void __launch_bounds__(256)
add_ln2_kernel(const float* __restrict__ a, const float* __restrict__ res,
               const float* __restrict__ g, const float* __restrict__ be,
               float* __restrict__ out)
{
    __shared__ float sm[8];
    long row = blockIdx.x;
    const float* ap = a + row * Dm;
    const float* rp = res + row * Dm;
    int t = threadIdx.x;
    float v0 = fmaxf(ap[t], 0.f) + rp[t];
    float v1 = fmaxf(ap[t + 256], 0.f) + rp[t + 256];
    float mean = block_sum(v0 + v1, sm) * (1.f / Dm);
    float d0 = v0 - mean, d1 = v1 - mean;
    float var = block_sum(d0 * d0 + d1 * d1, sm) * (1.f / Dm);
    float inv = rsqrtf(var + EPSv);
    out[row * Dm + t]       = d0 * inv * g[t]       + be[t];
    out[row * Dm + t + 256] = d1 * inv * g[t + 256] + be[t + 256];
}

// ---------------- launch ----------------
extern "C" void kernel_launch(void* const* d_in, const int* in_sizes, int n_in,
                              void* d_out, int out_size)
{
    const float* x    = (const float*)d_in[0];
    const float* Wq   = (const float*)d_in[1];
    const float* bq   = (const float*)d_in[2];
    const float* Wk   = (const float*)d_in[3];
    const float* bk   = (const float*)d_in[4];   (void)bk; // provably drops out of softmax
    const float* Wv   = (const float*)d_in[5];
    const float* bv   = (const float*)d_in[6];
    const float* Wo   = (const float*)d_in[7];
    const float* bo   = (const float*)d_in[8];
    const float* ln1g = (const float*)d_in[9];
    const float* ln1b = (const float*)d_in[10];
    const float* W1   = (const float*)d_in[11];
    const float* b1   = (const float*)d_in[12];
    const float* W2   = (const float*)d_in[13];
    const float* b2   = (const float*)d_in[14];
    const float* ln2g = (const float*)d_in[15];
    const float* ln2b = (const float*)d_in[16];
    float* out = (float*)d_out;

    bf16 *xh, *xl, *Wqh, *Wql, *Wkh, *Wkl, *Wvh, *Wvl, *WoTh, *WoTl;
    bf16 *W1Th, *W1Tl, *W2Th, *W2Tl, *Mth, *Mtl, *Nth, *Ntl;
    bf16 *uh, *ul, *zth, *ztl, *ph, *pl, *y1h, *y1l, *f1h, *f1l;
    float *w0, *ccp, *ps, *parts, *py1, *pff2;
    cudaGetSymbolAddress((void**)&xh, g_xh);     cudaGetSymbolAddress((void**)&xl, g_xl);
    cudaGetSymbolAddress((void**)&Wqh, g_Wqh);   cudaGetSymbolAddress((void**)&Wql, g_Wql);
    cudaGetSymbolAddress((void**)&Wkh, g_Wkh);   cudaGetSymbolAddress((void**)&Wkl, g_Wkl);
    cudaGetSymbolAddress((void**)&Wvh, g_Wvh);   cudaGetSymbolAddress((void**)&Wvl, g_Wvl);
    cudaGetSymbolAddress((void**)&WoTh, g_WoTh); cudaGetSymbolAddress((void**)&WoTl, g_WoTl);
    cudaGetSymbolAddress((void**)&W1Th, g_W1Th); cudaGetSymbolAddress((void**)&W1Tl, g_W1Tl);
    cudaGetSymbolAddress((void**)&W2Th, g_W2Th); cudaGetSymbolAddress((void**)&W2Tl, g_W2Tl);
    cudaGetSymbolAddress((void**)&Mth, g_Mth);   cudaGetSymbolAddress((void**)&Mtl, g_Mtl);
    cudaGetSymbolAddress((void**)&Nth, g_Nth);   cudaGetSymbolAddress((void**)&Ntl, g_Ntl);
    cudaGetSymbolAddress((void**)&w0, g_w0);     cudaGetSymbolAddress((void**)&ccp, g_ccp);
    cudaGetSymbolAddress((void**)&uh, g_uh);     cudaGetSymbolAddress((void**)&ul, g_ul);
    cudaGetSymbolAddress((void**)&zth, g_zth);   cudaGetSymbolAddress((void**)&ztl, g_ztl);
    cudaGetSymbolAddress((void**)&ps, g_s);
    cudaGetSymbolAddress((void**)&ph, g_ph);     cudaGetSymbolAddress((void**)&pl, g_pl);
    cudaGetSymbolAddress((void**)&parts, g_parts);
    cudaGetSymbolAddress((void**)&py1, g_y1);
    cudaGetSymbolAddress((void**)&y1h, g_y1h);   cudaGetSymbolAddress((void**)&y1l, g_y1l);
    cudaGetSymbolAddress((void**)&f1h, g_f1h);   cudaGetSymbolAddress((void**)&f1l, g_f1l);
    cudaGetSymbolAddress((void**)&pff2, g_ff2);

    const float inv_sqrt_d = 0.044194173824159216f;
    const long DD = (long)Dm * Dm;

    // 0-3: splits + vecprep
    esplit<<<(BT * Dm + 255) / 256, 256>>>(x, xh, xl, BT * Dm);
    esplit<<<(HH * Dm * Dm + 255) / 256, 256>>>(Wq, Wqh, Wql, HH * Dm * Dm);
    esplit<<<(HH * Dm * Dm + 255) / 256, 256>>>(Wk, Wkh, Wkl, HH * Dm * Dm);
    vecprep<<<520, 256>>>(Wk, bq, Wo, bv, w0, ccp);

    // 4: Mt_h = Wk_h @ Wq_h^T  (so Mt[d'][d] = M[d][d'])
    gemm_mma<2><<<dim3(4, 4, HH), 256, SMEM_BYTES>>>(Wkh, Wkl, Wqh, Wql, nullptr,
        nullptr, Mth, Mtl, Dm, Dm, Dm, Dm, DD, DD, 0, 0L, 1, DD, 0L, 1.f);

    // 5: u = x @ M_h + w0_h   (B = Mt)   [H, BT, D] planes      <-- ncu target
    gemm_mma<2><<<dim3(4, BT / 128, HH), 256, SMEM_BYTES>>>(xh, xl, Mth, Mtl, w0,
        nullptr, uh, ul, Dm, Dm, Dm, Dm, 0L, DD, 0, (long)Dm, 1, (long)BT * Dm, 0L, 1.f);

    // 6-7: remaining splits
    esplit<<<(HH * Dm * Dm + 255) / 256, 256>>>(Wv, Wvh, Wvl, HH * Dm * Dm);
    tsplit<<<dim3(Dm / 32, (HH * Dm) / 32, 1), 256>>>(Wo, WoTh, WoTl, HH * Dm, Dm, 0L, 0L);

    // 8: Nt_h = WoT_h @ Wv_h^T  (Nt[e][d] = N[d][e])
    gemm_mma<2><<<dim3(4, 4, HH), 256, SMEM_BYTES>>>(WoTh, WoTl, Wvh, Wvl, nullptr,
        nullptr, Nth, Ntl, Dm, HH * Dm, Dm, Dm, (long)Dm, DD, 0, 0L, 1, DD, 0L, 1.f);

    // 9: z^T = (x @ N_h)^T  -> [H, B, D, T] planes (EPI=4)
    gemm_mma<4><<<dim3(4, BT / 128, HH), 256, SMEM_BYTES>>>(xh, xl, Nth, Ntl, nullptr,
        nullptr, zth, ztl, Dm, Dm, Dm, 0, 0L, DD, 0, 0L, 1, 0L, 0L, 1.f);

    // 10: scores = u @ x^T * 1/sqrt(D)   (B = x planes, shared per batch: modB = BB)
    gemm_mma<1><<<dim3(TT / 128, TT / 128, HH * BB), 256, SMEM_BYTES>>>(uh, ul, xh, xl,
        nullptr, ps, nullptr, nullptr, Dm, Dm, Dm, TT,
        (long)TT * Dm, (long)TT * Dm, BB, 0L, 1, (long)TT * TT, 0L, inv_sqrt_d);

    // 11: softmax -> P planes
    softmax_kernel<<<HH * BB * TT, 256>>>(ps, ph, pl);

    // 12: parts[h,b] = P @ z  (fp32, per-head)
    gemm_mma<1><<<dim3(Dm / 128, TT / 128, HH * BB), 256, SMEM_BYTES>>>(ph, pl, zth, ztl,
        nullptr, parts, nullptr, nullptr, TT, TT, TT, Dm,
        (long)TT * TT, (long)Dm * TT, 0, 0L, 1, (long)TT * Dm, 0L, 1.f);

    // 13: y1 = LN(sum_h parts + cc + bo + x)
    reduce_ln1<<<BT, 256>>>(parts, x, ccp, bo, ln1g, ln1b, py1, y1h, y1l);

    // 14-15: FFN weight splits
    tsplit<<<dim3(DFFm / 32, Dm / 32, 1), 256>>>(W1, W1Th, W1Tl, Dm, DFFm, 0L, 0L);
    tsplit<<<dim3(Dm / 32, DFFm / 32, 1), 256>>>(W2, W2Th, W2Tl, DFFm, Dm, 0L, 0L);

    // 16: FFN1 -> f1 planes
    gemm_mma<2><<<dim3(DFFm / 128, BT / 128, 1), 256, SMEM_BYTES>>>(y1h, y1l, W1Th, W1Tl,
        b1, nullptr, f1h, f1l, Dm, Dm, Dm, DFFm, 0L, 0L, 0, 0L, 1, 0L, 0L, 1.f);

    // 17: FFN2 -> ff2 fp32
    gemm_mma<1><<<dim3(Dm / 128, BT / 128, 1), 256, SMEM_BYTES>>>(f1h, f1l, W2Th, W2Tl,
        b2, pff2, nullptr, nullptr, DFFm, DFFm, DFFm, Dm, 0L, 0L, 0, 0L, 1, 0L, 0L, 1.f);

    // 18: out = LN(relu(ff2) + y1)
    add_ln2_kernel<<<BT, 256>>>(pff2, py1, ln2g, ln2b, out);
}